// round 11
// baseline (speedup 1.0000x reference)
#include <cuda_runtime.h>

#define IMG_H 512
#define IMG_W 512
#define OUT_H 506
#define OUT_W 506
#define BAND  34      // output rows per band (bands 0..13), last band = 30
#define NBANDS 15
#define LASTB (OUT_H - (NBANDS - 1) * BAND)   // 30

typedef unsigned long long u64;

__device__ double g_acc;        // zero at module load; self-reset each launch
__device__ unsigned g_count;    // wraps to 0 via atomicInc each launch

__device__ __forceinline__ u64 pack2(float lo, float hi) {
    u64 r; asm("mov.b64 %0, {%1, %2};" : "=l"(r) : "f"(lo), "f"(hi)); return r;
}
__device__ __forceinline__ void unpack2(u64 v, float& lo, float& hi) {
    asm("mov.b64 {%0, %1}, %2;" : "=f"(lo), "=f"(hi) : "l"(v));
}
__device__ __forceinline__ u64 add2(u64 a, u64 b) {
    u64 r; asm("add.rn.f32x2 %0, %1, %2;" : "=l"(r) : "l"(a), "l"(b)); return r;
}
__device__ __forceinline__ u64 mul2(u64 a, u64 b) {
    u64 r; asm("mul.rn.f32x2 %0, %1, %2;" : "=l"(r) : "l"(a), "l"(b)); return r;
}
__device__ __forceinline__ u64 fma2(u64 a, u64 b, u64 c) {
    u64 r; asm("fma.rn.f32x2 %0, %1, %2, %3;" : "=l"(r) : "l"(a), "l"(b), "l"(c)); return r;
}
__device__ __forceinline__ u64 sub2(u64 a, u64 b, u64 neg1) { return fma2(b, neg1, a); }

__device__ __forceinline__ u64 shfl_dn64(u64 v) {
    unsigned lo = (unsigned)v, hi = (unsigned)(v >> 32);
    lo = __shfl_down_sync(0xffffffffu, lo, 1);
    hi = __shfl_down_sync(0xffffffffu, hi, 1);
    return ((u64)hi << 32) | lo;
}

#define LDROW(R, BP, BT) do {                                              \
    const float4* _pp = (const float4*)(Pp + (size_t)(R) * IMG_W);         \
    const float4* _tp = (const float4*)(Tp + (size_t)(R) * IMG_W);         \
    _Pragma("unroll") for (int _i = 0; _i < 4; ++_i) {                     \
        BP[_i] = __ldg(_pp + _i); BT[_i] = __ldg(_tp + _i);                \
    } } while (0)

// add-only accumulate of one row (prologue + iter 0)
#define ACCG(i, BP, BT) do {                                               \
    const float4 _a = BP[i], _b = BT[i];                                   \
    u64 _w;                                                                \
    _w = pack2(_a.x, _b.x); CW[4*(i)+0] = add2(CW[4*(i)+0], _w);           \
    CQ[4*(i)+0] = fma2(_w, _w, CQ[4*(i)+0]);                               \
    _w = pack2(_a.y, _b.y); CW[4*(i)+1] = add2(CW[4*(i)+1], _w);           \
    CQ[4*(i)+1] = fma2(_w, _w, CQ[4*(i)+1]);                               \
    _w = pack2(_a.z, _b.z); CW[4*(i)+2] = add2(CW[4*(i)+2], _w);           \
    CQ[4*(i)+2] = fma2(_w, _w, CQ[4*(i)+2]);                               \
    _w = pack2(_a.w, _b.w); CW[4*(i)+3] = add2(CW[4*(i)+3], _w);           \
    CQ[4*(i)+3] = fma2(_w, _w, CQ[4*(i)+3]);                               \
    CU2[2*(i)]   = fma2(pack2(_a.x,_a.y), pack2(_b.x,_b.y), CU2[2*(i)]);   \
    CU2[2*(i)+1] = fma2(pack2(_a.z,_a.w), pack2(_b.z,_b.w), CU2[2*(i)+1]); \
    } while (0)
#define ACC(BP, BT) do { ACCG(0,BP,BT); ACCG(1,BP,BT); ACCG(2,BP,BT); ACCG(3,BP,BT); } while (0)

// fused slide: add new row, subtract old row, via diff/sum factorization
#define FUSEDG(i, NPv, NTv, OPv, OTv) do {                                 \
    const float4 _an = NPv[i], _bn = NTv[i], _ao = OPv[i], _bo = OTv[i];   \
    u64 _wn, _wo, _d, _s;                                                  \
    _wn = pack2(_an.x,_bn.x); _wo = pack2(_ao.x,_bo.x);                    \
    _d = sub2(_wn,_wo,NEG1); _s = add2(_wn,_wo);                           \
    CW[4*(i)+0] = add2(CW[4*(i)+0], _d);                                   \
    CQ[4*(i)+0] = fma2(_d, _s, CQ[4*(i)+0]);                               \
    _wn = pack2(_an.y,_bn.y); _wo = pack2(_ao.y,_bo.y);                    \
    _d = sub2(_wn,_wo,NEG1); _s = add2(_wn,_wo);                           \
    CW[4*(i)+1] = add2(CW[4*(i)+1], _d);                                   \
    CQ[4*(i)+1] = fma2(_d, _s, CQ[4*(i)+1]);                               \
    _wn = pack2(_an.z,_bn.z); _wo = pack2(_ao.z,_bo.z);                    \
    _d = sub2(_wn,_wo,NEG1); _s = add2(_wn,_wo);                           \
    CW[4*(i)+2] = add2(CW[4*(i)+2], _d);                                   \
    CQ[4*(i)+2] = fma2(_d, _s, CQ[4*(i)+2]);                               \
    _wn = pack2(_an.w,_bn.w); _wo = pack2(_ao.w,_bo.w);                    \
    _d = sub2(_wn,_wo,NEG1); _s = add2(_wn,_wo);                           \
    CW[4*(i)+3] = add2(CW[4*(i)+3], _d);                                   \
    CQ[4*(i)+3] = fma2(_d, _s, CQ[4*(i)+3]);                               \
    {   u64 _un = mul2(pack2(_an.x,_an.y), pack2(_bn.x,_bn.y));            \
        u64 _uo = mul2(pack2(_ao.x,_ao.y), pack2(_bo.x,_bo.y));            \
        CU2[2*(i)]   = add2(CU2[2*(i)], _un);                              \
        CU2[2*(i)]   = sub2(CU2[2*(i)], _uo, NEG1); }                      \
    {   u64 _un = mul2(pack2(_an.z,_an.w), pack2(_bn.z,_bn.w));            \
        u64 _uo = mul2(pack2(_ao.z,_ao.w), pack2(_bo.z,_bo.w));            \
        CU2[2*(i)+1] = add2(CU2[2*(i)+1], _un);                            \
        CU2[2*(i)+1] = sub2(CU2[2*(i)+1], _uo, NEG1); }                    \
    } while (0)
#define FUSED(NPv,NTv,OPv,OTv) do { FUSEDG(0,NPv,NTv,OPv,OTv); FUSEDG(1,NPv,NTv,OPv,OTv); \
                                    FUSEDG(2,NPv,NTv,OPv,OTv); FUSEDG(3,NPv,NTv,OPv,OTv); } while (0)

#define GW(J) ((J) < 16 ? CW[(J)] : hW[(J) - 16])
#define GQ(J) ((J) < 16 ? CQ[(J)] : hQ[(J) - 16])

#define EMIT() do {                                                         \
    u64 hW[6], hQ[6], hU2[3];                                               \
    _Pragma("unroll") for (int _k = 0; _k < 6; ++_k) {                      \
        hW[_k] = shfl_dn64(CW[_k]); hQ[_k] = shfl_dn64(CQ[_k]);             \
    }                                                                       \
    _Pragma("unroll") for (int _k = 0; _k < 3; ++_k)                        \
        hU2[_k] = shfl_dn64(CU2[_k]);                                       \
    float Ua[22];                                                           \
    _Pragma("unroll") for (int _k = 0; _k < 8; ++_k)                        \
        unpack2(CU2[_k], Ua[2*_k], Ua[2*_k+1]);                             \
    _Pragma("unroll") for (int _k = 0; _k < 3; ++_k)                        \
        unpack2(hU2[_k], Ua[16+2*_k], Ua[17+2*_k]);                         \
    u64 VW = add2(add2(add2(CW[0],CW[1]),add2(CW[2],CW[3])),                \
                  add2(add2(CW[4],CW[5]),CW[6]));                           \
    u64 VQ = add2(add2(add2(CQ[0],CQ[1]),add2(CQ[2],CQ[3])),                \
                  add2(add2(CQ[4],CQ[5]),CQ[6]));                           \
    float VU = ((Ua[0]+Ua[1])+(Ua[2]+Ua[3]))+((Ua[4]+Ua[5])+Ua[6]);         \
    float gr = 0.f, gq = 1.f;                                               \
    _Pragma("unroll") for (int j = 0; j < 16; j += 2) {                     \
        u64 VW1 = add2(sub2(VW, GW(j), NEG1), GW(j+7));                     \
        u64 VQ1 = add2(sub2(VQ, GQ(j), NEG1), GQ(j+7));                     \
        float VU1 = VU - Ua[j] + Ua[j+7];                                   \
        float wx0,wy0,wx1,wy1,qx0,qy0,qx1,qy1;                              \
        unpack2(VW, wx0, wy0); unpack2(VW1, wx1, wy1);                      \
        unpack2(VQ, qx0, qy0); unpack2(VQ1, qx1, qy1);                      \
        const u64 X  = pack2(wx0, wx1), Y  = pack2(wy0, wy1);               \
        const u64 XX = pack2(qx0, qx1), YY = pack2(qy0, qy1);               \
        const u64 Uu = pack2(VU, VU1);                                      \
        const u64 SXY = mul2(X, Y);                                         \
        const u64 N1v = fma2(C_TWO, SXY, C_A);                              \
        const u64 CCv = fma2(C_49, Uu, mul2(SXY, NEG1));                    \
        const u64 N2v = fma2(C_2Q, CCv, C_B);                               \
        const u64 S2v = fma2(X, X, mul2(Y, Y));                             \
        const u64 D1v = add2(S2v, C_A);                                     \
        const u64 TTv = fma2(C_49, add2(XX, YY), mul2(S2v, NEG1));          \
        const u64 D2v = fma2(C_Q, TTv, C_B);                                \
        const u64 NUMv = mul2(N1v, N2v), DENv = mul2(D1v, D2v);             \
        float n0, n1, d0, d1;                                               \
        unpack2(NUMv, n0, n1); unpack2(DENv, d0, d1);                       \
        if (j >= 10) {   /* only cols >= 506 can be invalid (lane 31) */    \
            if (cb + j     >= OUT_W) { n0 = 0.f; d0 = 1.f; }                \
            if (cb + j + 1 >= OUT_W) { n1 = 0.f; d1 = 1.f; }                \
        }                                                                   \
        const float r2 = fmaf(n0, d1, n1 * d0);                             \
        const float q2 = d0 * d1;                                           \
        if ((j & 2) == 0) { gr = r2; gq = q2; }                             \
        else { acc += __fdividef(fmaf(gr, q2, r2 * gq), gq * q2); }         \
        if (j < 14) {                                                       \
            VW = add2(sub2(VW1, GW(j+1), NEG1), GW(j+8));                   \
            VQ = add2(sub2(VQ1, GQ(j+1), NEG1), GQ(j+8));                   \
            VU = VU1 - Ua[j+1] + Ua[j+8];                                   \
        }                                                                   \
    } } while (0)

__global__ void __launch_bounds__(32, 10) ssim_kernel(const float* __restrict__ pred,
                                                      const float* __restrict__ targ,
                                                      float* __restrict__ out,
                                                      double inv_count, unsigned nblk)
{
    const int lane  = threadIdx.x;
    const int plane = blockIdx.x / NBANDS;
    const int band  = blockIdx.x % NBANDS;
    const int rows  = (band == NBANDS - 1) ? LASTB : BAND;   // 30 or 34
    const size_t base = (size_t)plane * IMG_H * IMG_W
                      + (size_t)(band * BAND) * IMG_W + lane * 16;
    const float* __restrict__ Pp = pred + base;
    const float* __restrict__ Tp = targ + base;
    const int cb = lane * 16;

    const u64 NEG1  = pack2(-1.f, -1.f);
    const u64 C_TWO = pack2(2.f, 2.f);
    const u64 C_A   = pack2(0.96040004f, 0.96040004f);   // C1*49^2
    const u64 C_B   = pack2(8.6436f, 8.6436f);           // C2*49^2
    const u64 C_49  = pack2(49.f, 49.f);
    const u64 C_Q   = pack2(49.f/48.f, 49.f/48.f);
    const u64 C_2Q  = pack2(2.f*49.f/48.f, 2.f*49.f/48.f);

    u64 CW[16], CQ[16], CU2[8];
    #pragma unroll
    for (int i = 0; i < 16; ++i) { CW[i] = 0; CQ[i] = 0; }
    #pragma unroll
    for (int i = 0; i < 8; ++i) CU2[i] = 0;

    float4 PN0[4], TN0[4], PN1[4], TN1[4];   // new-row ping-pong
    float4 OP[4],  OT[4];                    // old-row single buffer
    float acc = 0.f;

    // prologue: accumulate rows 0..5 (ping-pong to overlap loads)
    LDROW(0, PN0, TN0);
    LDROW(1, PN1, TN1); ACC(PN0, TN0);
    LDROW(2, PN0, TN0); ACC(PN1, TN1);
    LDROW(3, PN1, TN1); ACC(PN0, TN0);
    LDROW(4, PN0, TN0); ACC(PN1, TN1);
    LDROW(5, PN1, TN1); ACC(PN0, TN0);
    ACC(PN1, TN1);
    LDROW(6, PN0, TN0);

    // iter 0: window rows 0..6 (add-only). EMIT(0) is deferred into the loop.
    LDROW(7, PN1, TN1);                      // new row for iter 1
    ACC(PN0, TN0);

    // iters 1..rows-1, pipelined: loads -> EMIT(prev window) -> FUSED(this window)
    #pragma unroll 1
    for (int r = 1; r < rows; r += 2) {
        // iter r: new row r+6 is in PN1; old row r-1 loaded now, used after EMIT
        if (r + 1 < rows) LDROW(r + 7, PN0, TN0);   // new for iter r+1
        LDROW(r - 1, OP, OT);
        EMIT();                               // window r-1
        FUSED(PN1, TN1, OP, OT);              // -> window r
        if (r + 1 < rows) {
            // iter r+1: new row r+7 in PN0; old row r
            if (r + 2 < rows) LDROW(r + 8, PN1, TN1);
            LDROW(r, OP, OT);
            EMIT();                           // window r
            FUSED(PN0, TN0, OP, OT);          // -> window r+1
        }
    }
    EMIT();                                   // final window (rows-1)

    // warp reduce -> atomic; last block finalizes and resets for graph replay
    #pragma unroll
    for (int off = 16; off > 0; off >>= 1)
        acc += __shfl_down_sync(0xffffffffu, acc, off);
    if (lane == 0) {
        atomicAdd(&g_acc, (double)acc);
        __threadfence();
        const unsigned old = atomicInc(&g_count, nblk - 1);
        if (old == nblk - 1) {
            __threadfence();
            const double v = atomicAdd(&g_acc, 0.0);
            out[0] = 1.0f - (float)(v * inv_count);
            __threadfence();
            g_acc = 0.0;
        }
    }
}

extern "C" void kernel_launch(void* const* d_in, const int* in_sizes, int n_in,
                              void* d_out, int out_size)
{
    const float* pred = (const float*)d_in[0];
    const float* targ = (const float*)d_in[1];
    const int planes = in_sizes[0] / (IMG_H * IMG_W);     // 96

    const unsigned blocks = (unsigned)planes * NBANDS;    // 1440
    const double inv_count = 1.0 / ((double)planes * OUT_H * OUT_W);

    ssim_kernel<<<blocks, 32>>>(pred, targ, (float*)d_out, inv_count, blocks);
}

// round 12
// speedup vs baseline: 1.5007x; 1.5007x over previous
#include <cuda_runtime.h>

#define IMG_H 512
#define IMG_W 512
#define OUT_H 506
#define OUT_W 506
#define BAND  42      // output rows per band; bands 10,11 do one extra row (506 = 10*42 + 2*43)
#define NBANDS 12

typedef unsigned long long u64;

__device__ double g_acc;        // zero at module load; self-reset each launch
__device__ unsigned g_count;    // wraps to 0 via atomicInc each launch

__device__ __forceinline__ u64 pack2(float lo, float hi) {
    u64 r; asm("mov.b64 %0, {%1, %2};" : "=l"(r) : "f"(lo), "f"(hi)); return r;
}
__device__ __forceinline__ void unpack2(u64 v, float& lo, float& hi) {
    asm("mov.b64 {%0, %1}, %2;" : "=f"(lo), "=f"(hi) : "l"(v));
}
__device__ __forceinline__ u64 add2(u64 a, u64 b) {
    u64 r; asm("add.rn.f32x2 %0, %1, %2;" : "=l"(r) : "l"(a), "l"(b)); return r;
}
__device__ __forceinline__ u64 mul2(u64 a, u64 b) {
    u64 r; asm("mul.rn.f32x2 %0, %1, %2;" : "=l"(r) : "l"(a), "l"(b)); return r;
}
__device__ __forceinline__ u64 fma2(u64 a, u64 b, u64 c) {
    u64 r; asm("fma.rn.f32x2 %0, %1, %2, %3;" : "=l"(r) : "l"(a), "l"(b), "l"(c)); return r;
}
__device__ __forceinline__ u64 sub2(u64 a, u64 b, u64 neg1) { return fma2(b, neg1, a); }

__device__ __forceinline__ u64 shfl_dn64(u64 v) {
    unsigned lo = (unsigned)v, hi = (unsigned)(v >> 32);
    lo = __shfl_down_sync(0xffffffffu, lo, 1);
    hi = __shfl_down_sync(0xffffffffu, hi, 1);
    return ((u64)hi << 32) | lo;
}

#define LDROW(R, BP, BT) do {                                              \
    const float4* _pp = (const float4*)(Pp + (size_t)(R) * IMG_W);         \
    const float4* _tp = (const float4*)(Tp + (size_t)(R) * IMG_W);         \
    _Pragma("unroll") for (int _i = 0; _i < 4; ++_i) {                     \
        BP[_i] = __ldg(_pp + _i); BT[_i] = __ldg(_tp + _i);                \
    } } while (0)

// add-only accumulate of one row (prologue + iter 0)
#define ACCG(i, BP, BT) do {                                               \
    const float4 _a = BP[i], _b = BT[i];                                   \
    u64 _w;                                                                \
    _w = pack2(_a.x, _b.x); CW[4*(i)+0] = add2(CW[4*(i)+0], _w);           \
    CQ[4*(i)+0] = fma2(_w, _w, CQ[4*(i)+0]);                               \
    _w = pack2(_a.y, _b.y); CW[4*(i)+1] = add2(CW[4*(i)+1], _w);           \
    CQ[4*(i)+1] = fma2(_w, _w, CQ[4*(i)+1]);                               \
    _w = pack2(_a.z, _b.z); CW[4*(i)+2] = add2(CW[4*(i)+2], _w);           \
    CQ[4*(i)+2] = fma2(_w, _w, CQ[4*(i)+2]);                               \
    _w = pack2(_a.w, _b.w); CW[4*(i)+3] = add2(CW[4*(i)+3], _w);           \
    CQ[4*(i)+3] = fma2(_w, _w, CQ[4*(i)+3]);                               \
    CU2[2*(i)]   = fma2(pack2(_a.x,_a.y), pack2(_b.x,_b.y), CU2[2*(i)]);   \
    CU2[2*(i)+1] = fma2(pack2(_a.z,_a.w), pack2(_b.z,_b.w), CU2[2*(i)+1]); \
    } while (0)
#define ACC(BP, BT) do { ACCG(0,BP,BT); ACCG(1,BP,BT); ACCG(2,BP,BT); ACCG(3,BP,BT); } while (0)

// fused slide: add new row, subtract old row, via diff/sum factorization
#define FUSEDG(i, NPv, NTv, OPv, OTv) do {                                 \
    const float4 _an = NPv[i], _bn = NTv[i], _ao = OPv[i], _bo = OTv[i];   \
    u64 _wn, _wo, _d, _s;                                                  \
    _wn = pack2(_an.x,_bn.x); _wo = pack2(_ao.x,_bo.x);                    \
    _d = sub2(_wn,_wo,NEG1); _s = add2(_wn,_wo);                           \
    CW[4*(i)+0] = add2(CW[4*(i)+0], _d);                                   \
    CQ[4*(i)+0] = fma2(_d, _s, CQ[4*(i)+0]);                               \
    _wn = pack2(_an.y,_bn.y); _wo = pack2(_ao.y,_bo.y);                    \
    _d = sub2(_wn,_wo,NEG1); _s = add2(_wn,_wo);                           \
    CW[4*(i)+1] = add2(CW[4*(i)+1], _d);                                   \
    CQ[4*(i)+1] = fma2(_d, _s, CQ[4*(i)+1]);                               \
    _wn = pack2(_an.z,_bn.z); _wo = pack2(_ao.z,_bo.z);                    \
    _d = sub2(_wn,_wo,NEG1); _s = add2(_wn,_wo);                           \
    CW[4*(i)+2] = add2(CW[4*(i)+2], _d);                                   \
    CQ[4*(i)+2] = fma2(_d, _s, CQ[4*(i)+2]);                               \
    _wn = pack2(_an.w,_bn.w); _wo = pack2(_ao.w,_bo.w);                    \
    _d = sub2(_wn,_wo,NEG1); _s = add2(_wn,_wo);                           \
    CW[4*(i)+3] = add2(CW[4*(i)+3], _d);                                   \
    CQ[4*(i)+3] = fma2(_d, _s, CQ[4*(i)+3]);                               \
    {   u64 _un = mul2(pack2(_an.x,_an.y), pack2(_bn.x,_bn.y));            \
        u64 _uo = mul2(pack2(_ao.x,_ao.y), pack2(_bo.x,_bo.y));            \
        CU2[2*(i)]   = add2(CU2[2*(i)], _un);                              \
        CU2[2*(i)]   = sub2(CU2[2*(i)], _uo, NEG1); }                      \
    {   u64 _un = mul2(pack2(_an.z,_an.w), pack2(_bn.z,_bn.w));            \
        u64 _uo = mul2(pack2(_ao.z,_ao.w), pack2(_bo.z,_bo.w));            \
        CU2[2*(i)+1] = add2(CU2[2*(i)+1], _un);                            \
        CU2[2*(i)+1] = sub2(CU2[2*(i)+1], _uo, NEG1); }                    \
    } while (0)
#define FUSED(NPv,NTv,OPv,OTv) do { FUSEDG(0,NPv,NTv,OPv,OTv); FUSEDG(1,NPv,NTv,OPv,OTv); \
                                    FUSEDG(2,NPv,NTv,OPv,OTv); FUSEDG(3,NPv,NTv,OPv,OTv); } while (0)

#define GW(J) ((J) < 16 ? CW[(J)] : hW[(J) - 16])
#define GQ(J) ((J) < 16 ? CQ[(J)] : hQ[(J) - 16])

#define EMIT() do {                                                         \
    u64 hW[6], hQ[6], hU2[3];                                               \
    _Pragma("unroll") for (int _k = 0; _k < 6; ++_k) {                      \
        hW[_k] = shfl_dn64(CW[_k]); hQ[_k] = shfl_dn64(CQ[_k]);             \
    }                                                                       \
    _Pragma("unroll") for (int _k = 0; _k < 3; ++_k)                        \
        hU2[_k] = shfl_dn64(CU2[_k]);                                       \
    float Ua[22];                                                           \
    _Pragma("unroll") for (int _k = 0; _k < 8; ++_k)                        \
        unpack2(CU2[_k], Ua[2*_k], Ua[2*_k+1]);                             \
    _Pragma("unroll") for (int _k = 0; _k < 3; ++_k)                        \
        unpack2(hU2[_k], Ua[16+2*_k], Ua[17+2*_k]);                         \
    u64 VW = add2(add2(add2(CW[0],CW[1]),add2(CW[2],CW[3])),                \
                  add2(add2(CW[4],CW[5]),CW[6]));                           \
    u64 VQ = add2(add2(add2(CQ[0],CQ[1]),add2(CQ[2],CQ[3])),                \
                  add2(add2(CQ[4],CQ[5]),CQ[6]));                           \
    float VU = ((Ua[0]+Ua[1])+(Ua[2]+Ua[3]))+((Ua[4]+Ua[5])+Ua[6]);         \
    float gr = 0.f, gq = 1.f;                                               \
    _Pragma("unroll") for (int j = 0; j < 16; j += 2) {                     \
        u64 VW1 = add2(sub2(VW, GW(j), NEG1), GW(j+7));                     \
        u64 VQ1 = add2(sub2(VQ, GQ(j), NEG1), GQ(j+7));                     \
        float VU1 = VU - Ua[j] + Ua[j+7];                                   \
        float wx0,wy0,wx1,wy1,qx0,qy0,qx1,qy1;                              \
        unpack2(VW, wx0, wy0); unpack2(VW1, wx1, wy1);                      \
        unpack2(VQ, qx0, qy0); unpack2(VQ1, qx1, qy1);                      \
        const u64 X  = pack2(wx0, wx1), Y  = pack2(wy0, wy1);               \
        const u64 XX = pack2(qx0, qx1), YY = pack2(qy0, qy1);               \
        const u64 Uu = pack2(VU, VU1);                                      \
        const u64 SXY = mul2(X, Y);                                         \
        const u64 N1v = fma2(C_TWO, SXY, C_A);                              \
        const u64 CCv = fma2(C_49, Uu, mul2(SXY, NEG1));                    \
        const u64 N2v = fma2(C_2Q, CCv, C_B);                               \
        const u64 S2v = fma2(X, X, mul2(Y, Y));                             \
        const u64 D1v = add2(S2v, C_A);                                     \
        const u64 TTv = fma2(C_49, add2(XX, YY), mul2(S2v, NEG1));          \
        const u64 D2v = fma2(C_Q, TTv, C_B);                                \
        const u64 NUMv = mul2(N1v, N2v), DENv = mul2(D1v, D2v);             \
        float n0, n1, d0, d1;                                               \
        unpack2(NUMv, n0, n1); unpack2(DENv, d0, d1);                       \
        if (j >= 10) {   /* only cols >= 506 can be invalid (lane 31) */    \
            if (cb + j     >= OUT_W) { n0 = 0.f; d0 = 1.f; }                \
            if (cb + j + 1 >= OUT_W) { n1 = 0.f; d1 = 1.f; }                \
        }                                                                   \
        const float r2 = fmaf(n0, d1, n1 * d0);                             \
        const float q2 = d0 * d1;                                           \
        if ((j & 2) == 0) { gr = r2; gq = q2; }                             \
        else { acc += __fdividef(fmaf(gr, q2, r2 * gq), gq * q2); }         \
        if (j < 14) {                                                       \
            VW = add2(sub2(VW1, GW(j+1), NEG1), GW(j+8));                   \
            VQ = add2(sub2(VQ1, GQ(j+1), NEG1), GQ(j+8));                   \
            VU = VU1 - Ua[j+1] + Ua[j+8];                                   \
        }                                                                   \
    } } while (0)

__global__ void __launch_bounds__(32, 8) ssim_kernel(const float* __restrict__ pred,
                                                     const float* __restrict__ targ,
                                                     float* __restrict__ out,
                                                     double inv_count, unsigned nblk)
{
    const int lane  = threadIdx.x;
    const int plane = blockIdx.x / NBANDS;
    const int band  = blockIdx.x % NBANDS;
    // bands 0..9 start at 42*band, 42 rows; bands 10,11 start at 420/463, 43 rows
    const int y0 = band * BAND + ((band > 10) ? (band - 10) : 0);
    const bool extra_row = (band >= 10);
    const size_t base = (size_t)plane * IMG_H * IMG_W
                      + (size_t)y0 * IMG_W + lane * 16;
    const float* __restrict__ Pp = pred + base;
    const float* __restrict__ Tp = targ + base;
    const int cb = lane * 16;

    const u64 NEG1  = pack2(-1.f, -1.f);
    const u64 C_TWO = pack2(2.f, 2.f);
    const u64 C_A   = pack2(0.96040004f, 0.96040004f);   // C1*49^2
    const u64 C_B   = pack2(8.6436f, 8.6436f);           // C2*49^2
    const u64 C_49  = pack2(49.f, 49.f);
    const u64 C_Q   = pack2(49.f/48.f, 49.f/48.f);
    const u64 C_2Q  = pack2(2.f*49.f/48.f, 2.f*49.f/48.f);

    u64 CW[16], CQ[16], CU2[8];
    #pragma unroll
    for (int i = 0; i < 16; ++i) { CW[i] = 0; CQ[i] = 0; }
    #pragma unroll
    for (int i = 0; i < 8; ++i) CU2[i] = 0;

    float4 PN0[4], TN0[4], PN1[4], TN1[4];   // new-row ping-pong
    float4 PO0[4], TO0[4], PO1[4], TO1[4];   // old-row ping-pong (one iter ahead)
    float acc = 0.f;

    // prologue: accumulate rows 0..5 (ping-pong to overlap loads)
    LDROW(0, PN0, TN0);
    LDROW(1, PN1, TN1); ACC(PN0, TN0);
    LDROW(2, PN0, TN0); ACC(PN1, TN1);
    LDROW(3, PN1, TN1); ACC(PN0, TN0);
    LDROW(4, PN0, TN0); ACC(PN1, TN1);
    LDROW(5, PN1, TN1); ACC(PN0, TN0);
    ACC(PN1, TN1);
    LDROW(6, PN0, TN0);                       // new row for iter 0
    #pragma unroll
    for (int i = 0; i < 4; ++i) {             // old "row -1" = zeros for iter 0
        PO0[i] = make_float4(0.f,0.f,0.f,0.f);
        TO0[i] = make_float4(0.f,0.f,0.f,0.f);
    }

    #pragma unroll 1
    for (int r = 0; r < BAND; r += 2) {
        // ---- even iter r: window rows r..r+6, consumes PN0 (row r+6), PO0 (row r-1)
        LDROW(r + 7, PN1, TN1);               // new for iter r+1 (row <= 47, in-bounds)
        LDROW(r,     PO1, TO1);               // old for iter r+1
        FUSED(PN0, TN0, PO0, TO0);
        EMIT();
        // ---- odd iter r+1: consumes PN1 (row r+7), PO1 (row r)
        if (r + 2 < BAND) LDROW(r + 8, PN0, TN0);   // new for iter r+2
        LDROW(r + 1, PO0, TO0);               // old for iter r+2 (row <= 41)
        FUSED(PN1, TN1, PO1, TO1);
        EMIT();
    }

    // bands 10,11: one extra output row (window rows 42..48).
    // PO0 already holds old row 41 (loaded in the last loop pass).
    if (extra_row) {
        LDROW(BAND + 6, PN0, TN0);            // row 48; in-bounds (49 input rows)
        FUSED(PN0, TN0, PO0, TO0);
        EMIT();
    }

    // warp reduce -> atomic; last block finalizes and resets for graph replay
    #pragma unroll
    for (int off = 16; off > 0; off >>= 1)
        acc += __shfl_down_sync(0xffffffffu, acc, off);
    if (lane == 0) {
        atomicAdd(&g_acc, (double)acc);
        __threadfence();
        const unsigned old = atomicInc(&g_count, nblk - 1);
        if (old == nblk - 1) {
            __threadfence();
            const double v = atomicAdd(&g_acc, 0.0);
            out[0] = 1.0f - (float)(v * inv_count);
            __threadfence();
            g_acc = 0.0;
        }
    }
}

extern "C" void kernel_launch(void* const* d_in, const int* in_sizes, int n_in,
                              void* d_out, int out_size)
{
    const float* pred = (const float*)d_in[0];
    const float* targ = (const float*)d_in[1];
    const int planes = in_sizes[0] / (IMG_H * IMG_W);     // 96

    const unsigned blocks = (unsigned)planes * NBANDS;    // 1152
    const double inv_count = 1.0 / ((double)planes * OUT_H * OUT_W);

    ssim_kernel<<<blocks, 32>>>(pred, targ, (float*)d_out, inv_count, blocks);
}